// round 10
// baseline (speedup 1.0000x reference)
#include <cuda_runtime.h>

// Path signature, depth 3 — TWO-KERNEL split, round 10. path: (32,128,48) f32.
// Out per batch: [lvl1 48 | lvl2 2304 | lvl3 110592] = 112944.
//
// Kernel 1 (phase A): per (b,i,j) serial S2 recurrence over t; writes
// w[b,i,t,j] and PRE-DUPLICATED vd[b,t,k] = {v,v}; emits lvl1/lvl2.
// Kernel 2 (phase B): barrier-free rank-127 accumulation
//   S3[b,i,j,k] = sum_t w[b,i,t,j] * v[b,t,k]
// Grid (48,32): one i-plane per block, 96 thr = 12(j-grp) x 8(k-grp),
// per-thread 4j x 6k tile = 12 u64 accs, packed fma.rn.f32x2 along j.
// Inner loop: 4 LDG.128 + 12 FFMA2, no shared, no syncs, no movs.
// 1536 blocks x 3 warps @ <=68 regs -> ~31 warps/SM to hide L2 latency.

#define NB     32
#define LPATH  128
#define C      48
#define NSTEPS (LPATH - 1)          // 127
#define LVL2   (C * C)
#define STR    (C + LVL2 + C * C * C)   // 112944
#define OFF2   C
#define OFF3   (C + LVL2)

typedef unsigned long long u64;

// Static device scratch (allocation-free).
__device__ __align__(256) float  g_w [(size_t)NB * C * NSTEPS * C];   // [b][i][t][j] 37.5MB
__device__ __align__(256) float2 g_vd[(size_t)NB * NSTEPS * C];       // [b][t][k] dup, 1.5MB

__device__ __forceinline__ void ffma2(u64& d, u64 a, u64 b) {
    asm("fma.rn.f32x2 %0, %1, %2, %0;" : "+l"(d) : "l"(a), "l"(b));
}
__device__ __forceinline__ float2 unpk(u64 a) {
    float2 r;
    asm("mov.b64 {%0, %1}, %2;" : "=f"(r.x), "=f"(r.y) : "l"(a));
    return r;
}

// ---------------- Kernel 1: phase A ----------------
// block (48, 4): tx = j, ty = local i; grid (12, 32) -> 384 blocks.
__global__ __launch_bounds__(192)
void sig_phase_a(const float* __restrict__ path, float* __restrict__ out)
{
    const int j = threadIdx.x;                    // 0..47
    const int i = blockIdx.x * 4 + threadIdx.y;   // 0..47
    const int b = blockIdx.y;

    const float* pb = path + (size_t)b * LPATH * C;

    float p_j  = pb[j];
    float p0_i = pb[i];
    float p_i  = p0_i;
    float S2   = 0.0f;

    float*  wrow = g_w  + ((size_t)(b * C + i) * NSTEPS) * C + j;
    float2* vrow = g_vd + (size_t)b * NSTEPS * C + j;
    const bool wv = (i == 0);

#pragma unroll 4
    for (int t = 0; t < NSTEPS; ++t) {
        const float pn_j = pb[(t + 1) * C + j];   // coalesced
        const float pn_i = pb[(t + 1) * C + i];   // broadcast
        const float v_j = pn_j - p_j;
        const float v_i = pn_i - p_i;
        const float s1  = p_i - p0_i;
        wrow[(size_t)t * C] = fmaf(fmaf(1.0f / 6.0f, v_i, 0.5f * s1), v_j, S2);
        if (wv) vrow[(size_t)t * C] = make_float2(v_j, v_j);
        S2 = fmaf(fmaf(0.5f, v_i, s1), v_j, S2);
        p_j = pn_j;
        p_i = pn_i;
    }

    float* ob = out + (size_t)b * STR;
    ob[OFF2 + i * C + j] = S2;                 // level 2
    if (wv) ob[j] = p_j - pb[j];               // level 1 (p_j = path[127][j])
}

// ---------------- Kernel 2: phase B (barrier-free, high-occupancy) ----------
__global__ __launch_bounds__(96, 10)
void sig_phase_b(float* __restrict__ out)
{
    const int i   = blockIdx.x;   // 0..47  (one i-plane per block)
    const int b   = blockIdx.y;   // 0..31
    const int tid = threadIdx.x;  // 0..95

    const int jg = tid / 8;       // 0..11
    const int kg = tid % 8;       // 0..7
    const int j0 = jg * 4;        // 16B-aligned
    const int k0 = kg * 6;        // float2 index; byte offset 48*kg (16B-aligned)

    const float*  wp  = g_w  + ((size_t)(b * C + i) * NSTEPS) * C + j0;
    const float2* vdp = g_vd + (size_t)b * NSTEPS * C + k0;

    // acc[jp][kx]: f32x2 pair = rows (j0+2jp, j0+2jp+1), column k0+kx
    u64 acc[2][6];
#pragma unroll
    for (int jp = 0; jp < 2; ++jp)
#pragma unroll
        for (int kx = 0; kx < 6; ++kx) acc[jp][kx] = 0ull;

#pragma unroll 4
    for (int t = 0; t < NSTEPS; ++t) {
        const ulonglong2 W  = *(const ulonglong2*)(wp  + (size_t)t * C); // w[j0..j0+3]
        const ulonglong2 V0 = *(const ulonglong2*)(vdp + (size_t)t * C);     // k0,k0+1
        const ulonglong2 V1 = *(const ulonglong2*)(vdp + (size_t)t * C + 2); // k0+2,k0+3
        const ulonglong2 V2 = *(const ulonglong2*)(vdp + (size_t)t * C + 4); // k0+4,k0+5
        const u64 wa[2] = { W.x, W.y };
        const u64 vp[6] = { V0.x, V0.y, V1.x, V1.y, V2.x, V2.y };
#pragma unroll
        for (int jp = 0; jp < 2; ++jp)
#pragma unroll
            for (int kx = 0; kx < 6; ++kx)
                ffma2(acc[jp][kx], wa[jp], vp[kx]);
    }

    // ---- Epilogue: level 3 ----
    float* o3 = out + (size_t)b * STR + OFF3 + (size_t)i * LVL2;
#pragma unroll
    for (int jp = 0; jp < 2; ++jp) {
        float lo[6], hi[6];
#pragma unroll
        for (int kx = 0; kx < 6; ++kx) {
            const float2 a = unpk(acc[jp][kx]);
            lo[kx] = a.x; hi[kx] = a.y;
        }
        const int jlo = j0 + 2 * jp, jhi = jlo + 1;
#pragma unroll
        for (int kp = 0; kp < 3; ++kp) {   // 8B-aligned float2 stores
            *(float2*)&o3[jlo * C + k0 + 2 * kp] = make_float2(lo[2*kp], lo[2*kp+1]);
            *(float2*)&o3[jhi * C + k0 + 2 * kp] = make_float2(hi[2*kp], hi[2*kp+1]);
        }
    }
}

extern "C" void kernel_launch(void* const* d_in, const int* in_sizes, int n_in,
                              void* d_out, int out_size)
{
    (void)in_sizes; (void)n_in; (void)out_size;
    const float* path = (const float*)d_in[0];
    float* out = (float*)d_out;

    dim3 g1(12, NB), b1(48, 4);      // 384 blocks, 192 thr
    sig_phase_a<<<g1, b1>>>(path, out);

    dim3 g2(C, NB), b2(96);          // 1536 blocks, 96 thr
    sig_phase_b<<<g2, b2>>>(out);
}

// round 12
// speedup vs baseline: 1.4686x; 1.4686x over previous
#include <cuda_runtime.h>

// Path signature, depth 3 — fused kernel (R6 architecture, wide tile, FIXED
// thread mapping). path: (32, 128, 48) fp32. Out: [48 | 2304 | 110592]/batch.
//
// S3[i,j,k] = sum_t w[i][t][j] * v[t][k]
//   v[t][j]    = path[t+1][j] - path[t][j]
//   w[i][t][j] = S2prev[i][j] + (0.5*S1prev[i] + v[t][i]/6) * v[t][j]
//   S2[i][j]  += (S1prev[i] + 0.5*v[t][i]) * v[t][j]
//
// Block (bx,b): planes i0=2bx, i1=2bx+1. 96 threads = 12(j-grp) x 8(k-grp);
// per-thread tile 4j x 6k x 2 planes = 24 u64 f32x2 accumulators (paired
// along j; w pairs free from 16B shared loads, v dup'd via mov.b64).
// ALL 96 threads are producers (2 groups x 48). Chunk T=16, double-buffered
// shared, producers one chunk ahead, ONE barrier per stage (8 total).

#define NB     32
#define LPATH  128
#define C      48
#define NSTEPS (LPATH - 1)          // 127
#define LVL2   (C * C)
#define STR    (C + LVL2 + C * C * C)   // 112944
#define OFF2   C
#define OFF3   (C + LVL2)
#define TCH    16
#define NFULL  7                    // 7 full chunks of 16 = 112
#define TAILT  (NSTEPS - NFULL * TCH)   // 15

typedef unsigned long long u64;

__device__ __forceinline__ void ffma2(u64& d, u64 a, u64 b) {
    asm("fma.rn.f32x2 %0, %1, %2, %0;" : "+l"(d) : "l"(a), "l"(b));
}
__device__ __forceinline__ u64 dup_f32(float x) {
    u64 r;
    asm("mov.b64 %0, {%1, %1};" : "=l"(r) : "f"(x));
    return r;
}
__device__ __forceinline__ float2 unpk(u64 a) {
    float2 r;
    asm("mov.b64 {%0, %1}, %2;" : "=f"(r.x), "=f"(r.y) : "l"(a));
    return r;
}

// Phase A: every thread (96 = 2 groups x 48) produces one w row per step;
// group 0 also publishes v.
template<int T>
__device__ __forceinline__ void phase_a(
    const float* __restrict__ pb, int base_t, int buf, int i_r, int r, int jj,
    float& p_j, float& p_i, float p0_i, float& S2,
    float (*sh_v)[TCH][C], float (*sh_w)[2][TCH][C])
{
#pragma unroll
    for (int t = 0; t < T; ++t) {
        const float pn_j = pb[(base_t + t + 1) * C + jj];  // coalesced
        const float pn_i = pb[(base_t + t + 1) * C + i_r]; // broadcast
        const float v_j = pn_j - p_j;
        const float v_i = pn_i - p_i;
        const float s1  = p_i - p0_i;
        if (r == 0) sh_v[buf][t][jj] = v_j;
        sh_w[buf][r][t][jj] = fmaf(fmaf(1.0f / 6.0f, v_i, 0.5f * s1), v_j, S2);
        S2 = fmaf(fmaf(0.5f, v_i, s1), v_j, S2);
        p_j = pn_j;
        p_i = pn_i;
    }
}

// Phase B: T rank-1 updates of both 4j x 6k tiles (f32x2 packed along j).
template<int T>
__device__ __forceinline__ void phase_b(
    int buf, int j0, int k0, u64 (&acc0)[2][6], u64 (&acc1)[2][6],
    float (*sh_v)[TCH][C], float (*sh_w)[2][TCH][C])
{
#pragma unroll 2
    for (int t = 0; t < T; ++t) {
        const ulonglong2 W0 = *(const ulonglong2*)&sh_w[buf][0][t][j0];
        const ulonglong2 W1 = *(const ulonglong2*)&sh_w[buf][1][t][j0];
        const float2 vab = *(const float2*)&sh_v[buf][t][k0];      // 8B aligned
        const float2 vcd = *(const float2*)&sh_v[buf][t][k0 + 2];
        const float2 vef = *(const float2*)&sh_v[buf][t][k0 + 4];
        const u64 vp[6] = { dup_f32(vab.x), dup_f32(vab.y),
                            dup_f32(vcd.x), dup_f32(vcd.y),
                            dup_f32(vef.x), dup_f32(vef.y) };
        const u64 wa[2] = { W0.x, W0.y };   // j-pairs (j0,j0+1),(j0+2,j0+3)
        const u64 wb[2] = { W1.x, W1.y };
#pragma unroll
        for (int jp = 0; jp < 2; ++jp)
#pragma unroll
            for (int kx = 0; kx < 6; ++kx) {
                ffma2(acc0[jp][kx], wa[jp], vp[kx]);
                ffma2(acc1[jp][kx], wb[jp], vp[kx]);
            }
    }
}

__global__ __launch_bounds__(96, 6)
void sig_depth3_kernel(const float* __restrict__ path, float* __restrict__ out)
{
    const int bx  = blockIdx.x;   // 0..23 -> i0 = 2bx, i1 = 2bx+1
    const int b   = blockIdx.y;   // 0..31
    const int tid = threadIdx.x;  // 0..95

    __shared__ __align__(16) float sh_v[2][TCH][C];
    __shared__ __align__(16) float sh_w[2][2][TCH][C];

    const float* pb = path + (size_t)b * LPATH * C;

    u64 acc0[2][6], acc1[2][6];
#pragma unroll
    for (int jp = 0; jp < 2; ++jp)
#pragma unroll
        for (int kx = 0; kx < 6; ++kx) { acc0[jp][kx] = 0ull; acc1[jp][kx] = 0ull; }

    const int j0 = (tid / 8) * 4;   // 0,4,...,44  (12 j-groups)
    const int k0 = (tid % 8) * 6;   // 0,6,...,42  (8 k-groups, even -> 8B ok)

    // Producer identity: ALL 96 threads produce. Group r = i-plane.
    const int r   = (tid < C) ? 0 : 1;
    const int jj  = tid - r * C;    // 0..47
    const int i_r = 2 * bx + r;

    float p_j  = pb[jj];
    float p0_i = pb[i_r];
    float p_i  = p0_i;
    float S2   = 0.0f;

    // ---- Pipelined mainloop: A(s+1) before B(s), one barrier per stage ----
    phase_a<TCH>(pb, 0, 0, i_r, r, jj, p_j, p_i, p0_i, S2, sh_v, sh_w);
    __syncthreads();

#pragma unroll 1
    for (int s = 0; s < NFULL - 1; ++s) {   // s = 0..5
        phase_a<TCH>(pb, (s + 1) * TCH, (s + 1) & 1, i_r, r, jj,
                     p_j, p_i, p0_i, S2, sh_v, sh_w);
        phase_b<TCH>(s & 1, j0, k0, acc0, acc1, sh_v, sh_w);
        __syncthreads();
    }
    // Stage 6: produce tail (15 steps) into buf 1, consume chunk 6 (buf 0).
    phase_a<TAILT>(pb, NFULL * TCH, NFULL & 1, i_r, r, jj,
                   p_j, p_i, p0_i, S2, sh_v, sh_w);
    phase_b<TCH>((NFULL - 1) & 1, j0, k0, acc0, acc1, sh_v, sh_w);
    __syncthreads();
    phase_b<TAILT>(NFULL & 1, j0, k0, acc0, acc1, sh_v, sh_w);

    // ---- Epilogue ----
    float* ob = out + (size_t)b * STR;

    float* o30 = ob + OFF3 + (size_t)(2 * bx)     * LVL2;
    float* o31 = ob + OFF3 + (size_t)(2 * bx + 1) * LVL2;
#pragma unroll
    for (int jp = 0; jp < 2; ++jp) {
        float lo0[6], hi0[6], lo1[6], hi1[6];
#pragma unroll
        for (int kx = 0; kx < 6; ++kx) {
            const float2 a = unpk(acc0[jp][kx]); lo0[kx] = a.x; hi0[kx] = a.y;
            const float2 c = unpk(acc1[jp][kx]); lo1[kx] = c.x; hi1[kx] = c.y;
        }
        const int jlo = j0 + 2 * jp, jhi = jlo + 1;
#pragma unroll
        for (int kp = 0; kp < 3; ++kp) {    // float2 stores, 8B aligned
            *(float2*)&o30[jlo * C + k0 + 2 * kp] = make_float2(lo0[2*kp], lo0[2*kp+1]);
            *(float2*)&o30[jhi * C + k0 + 2 * kp] = make_float2(hi0[2*kp], hi0[2*kp+1]);
            *(float2*)&o31[jlo * C + k0 + 2 * kp] = make_float2(lo1[2*kp], lo1[2*kp+1]);
            *(float2*)&o31[jhi * C + k0 + 2 * kp] = make_float2(hi1[2*kp], hi1[2*kp+1]);
        }
    }

    // Levels 1-2 (every thread owns one (i_r, jj) cell).
    ob[OFF2 + i_r * C + jj] = S2;
    if (bx == 0 && r == 0) {
        // p_j now holds path[b][127][jj]
        ob[jj] = p_j - pb[jj];
    }
}

extern "C" void kernel_launch(void* const* d_in, const int* in_sizes, int n_in,
                              void* d_out, int out_size)
{
    (void)in_sizes; (void)n_in; (void)out_size;
    const float* path = (const float*)d_in[0];
    float* out = (float*)d_out;
    dim3 grid(C / 2, NB);   // (i-pairs, batch) = (24, 32)
    dim3 block(96);
    sig_depth3_kernel<<<grid, block>>>(path, out);
}